// round 5
// baseline (speedup 1.0000x reference)
#include <cuda_runtime.h>
#include <math.h>

#define SEQ      4096
#define HID      2048
#define NH       16
#define HD       128
#define HALF_WIN 256
#define NGLOB    16
#define SCALE    0.08838834764831845f   // 128^-0.5

// Scratch (device globals: allocation-free rule)
__device__ float g_Q[SEQ * HID];
__device__ float g_K[SEQ * HID];
__device__ float g_V[SEQ * HID];
__device__ float g_A[SEQ * HID];

// ---------------------------------------------------------------------------
// GEMM: C[M,N] = A[M,K] @ B[K,N], all row-major fp32.
// 128x128 tile, BK=8, 256 threads, 8x8 per-thread microtile.
// ---------------------------------------------------------------------------
__global__ __launch_bounds__(256) void gemm_kernel(
    const float* __restrict__ A, const float* __restrict__ B,
    float* __restrict__ C, int M, int N, int K)
{
    __shared__ float As[8][128];   // transposed: As[k][m]
    __shared__ float Bs[8][128];   // Bs[k][n]

    const int tid  = threadIdx.x;
    const int row0 = blockIdx.y * 128;
    const int col0 = blockIdx.x * 128;
    const int ty   = tid >> 4;     // 0..15
    const int tx   = tid & 15;     // 0..15

    // load indices
    const int ar = tid >> 1;           // 0..127
    const int ac = (tid & 1) << 2;     // 0 or 4
    const int br = tid >> 5;           // 0..7
    const int bc = (tid & 31) << 2;    // 0..124

    const float* Aptr = A + (size_t)row0 * K;
    const float* Bptr = B + col0;

    float acc[8][8];
#pragma unroll
    for (int i = 0; i < 8; i++)
#pragma unroll
        for (int j = 0; j < 8; j++) acc[i][j] = 0.0f;

    for (int k0 = 0; k0 < K; k0 += 8) {
        float4 av = *(const float4*)(Aptr + (size_t)ar * K + k0 + ac);
        float4 bv = *(const float4*)(Bptr + (size_t)(k0 + br) * N + bc);
        As[ac + 0][ar] = av.x;
        As[ac + 1][ar] = av.y;
        As[ac + 2][ar] = av.z;
        As[ac + 3][ar] = av.w;
        *(float4*)&Bs[br][bc] = bv;
        __syncthreads();

#pragma unroll
        for (int kc = 0; kc < 8; kc++) {
            float a[8], b[8];
            *(float4*)&a[0] = *(const float4*)&As[kc][ty * 8];
            *(float4*)&a[4] = *(const float4*)&As[kc][ty * 8 + 4];
            *(float4*)&b[0] = *(const float4*)&Bs[kc][tx * 8];
            *(float4*)&b[4] = *(const float4*)&Bs[kc][tx * 8 + 4];
#pragma unroll
            for (int i = 0; i < 8; i++)
#pragma unroll
                for (int j = 0; j < 8; j++)
                    acc[i][j] = fmaf(a[i], b[j], acc[i][j]);
        }
        __syncthreads();
    }

#pragma unroll
    for (int i = 0; i < 8; i++) {
        float* Crow = C + (size_t)(row0 + ty * 8 + i) * N + col0 + tx * 8;
        *(float4*)&Crow[0] = make_float4(acc[i][0], acc[i][1], acc[i][2], acc[i][3]);
        *(float4*)&Crow[4] = make_float4(acc[i][4], acc[i][5], acc[i][6], acc[i][7]);
    }
}

// ---------------------------------------------------------------------------
// Flash-attention with sliding-window + global mask.
// Block: 64 queries of one head. 256 threads (ty 0..15, tx 0..15).
// S tile: thread owns rows 4*ty..+3, cols 4*tx..+3.
// O accum: thread owns rows 4*ty..+3, cols 8*tx..+7.
// ---------------------------------------------------------------------------
#define QS_STRIDE 129
#define PS_STRIDE 65
#define SMEM_FLOATS (64 * QS_STRIDE * 2 + 64 * 128 + 64 * PS_STRIDE)
#define SMEM_BYTES  (SMEM_FLOATS * 4)

__global__ __launch_bounds__(256) void attn_kernel(
    const float* __restrict__ Q, const float* __restrict__ K,
    const float* __restrict__ V, float* __restrict__ O)
{
    extern __shared__ float smem[];
    float* Qs = smem;                       // [64][129]
    float* Ks = Qs + 64 * QS_STRIDE;        // [64][129]
    float* Vs = Ks + 64 * QS_STRIDE;        // [64][128]
    float* Ps = Vs + 64 * 128;              // [64][65]

    const int tid = threadIdx.x;
    const int ty  = tid >> 4;
    const int tx  = tid & 15;
    const int ty4 = ty * 4;
    const int tx4 = tx * 4;
    const int tx8 = tx * 8;
    const int q0  = blockIdx.x * 64;
    const int h   = blockIdx.y;

    // Load Q tile [64][128] (each thread: 8 float4)
    for (int s = tid; s < 64 * 32; s += 256) {
        int r  = s >> 5;
        int c4 = (s & 31) << 2;
        float4 v = *(const float4*)&Q[(size_t)(q0 + r) * HID + h * HD + c4];
        float* d = &Qs[r * QS_STRIDE + c4];
        d[0] = v.x; d[1] = v.y; d[2] = v.z; d[3] = v.w;
    }

    float m[4], l[4], acc[4][8];
#pragma unroll
    for (int i = 0; i < 4; i++) {
        m[i] = -INFINITY;
        l[i] = 0.0f;
#pragma unroll
        for (int j = 0; j < 8; j++) acc[i][j] = 0.0f;
    }

    // KV tile range: tile 0 always first (globals), then band tiles.
    int t_lo, t_hi;
    if (q0 == 0) {
        t_lo = 1; t_hi = 63;                       // global queries see everything
    } else {
        int lo = q0 - (HALF_WIN - 1);              // band start
        t_lo = (lo < 64) ? 1 : (lo >> 6);
        t_hi = (q0 + 63 + HALF_WIN - 1) >> 6;
        if (t_hi > 63) t_hi = 63;
    }

    for (int it = -1;; it++) {
        int t;
        if (it < 0) t = 0;
        else { t = t_lo + it; if (t > t_hi) break; }
        const int kv0 = t << 6;

        __syncthreads();   // previous tile's Ps/Vs reads done
        for (int s = tid; s < 64 * 32; s += 256) {
            int r  = s >> 5;
            int c4 = (s & 31) << 2;
            float4 kv = *(const float4*)&K[(size_t)(kv0 + r) * HID + h * HD + c4];
            float* kd = &Ks[r * QS_STRIDE + c4];
            kd[0] = kv.x; kd[1] = kv.y; kd[2] = kv.z; kd[3] = kv.w;
            float4 vv = *(const float4*)&V[(size_t)(kv0 + r) * HID + h * HD + c4];
            *(float4*)&Vs[r * 128 + c4] = vv;
        }
        __syncthreads();

        // S = Q @ K^T (4x4 per thread)
        float sv[4][4];
#pragma unroll
        for (int i = 0; i < 4; i++)
#pragma unroll
            for (int j = 0; j < 4; j++) sv[i][j] = 0.0f;

#pragma unroll 8
        for (int k = 0; k < 128; k++) {
            float a[4], b[4];
#pragma unroll
            for (int i = 0; i < 4; i++) a[i] = Qs[(ty4 + i) * QS_STRIDE + k];
#pragma unroll
            for (int j = 0; j < 4; j++) b[j] = Ks[(tx4 + j) * QS_STRIDE + k];
#pragma unroll
            for (int i = 0; i < 4; i++)
#pragma unroll
                for (int j = 0; j < 4; j++)
                    sv[i][j] = fmaf(a[i], b[j], sv[i][j]);
        }

        // mask + scale
#pragma unroll
        for (int i = 0; i < 4; i++) {
            const int qi = q0 + ty4 + i;
#pragma unroll
            for (int j = 0; j < 4; j++) {
                const int kj = kv0 + tx4 + j;
                const int d  = qi - kj;
                const bool ok = (d < HALF_WIN && d > -HALF_WIN) || (qi < NGLOB) || (kj < NGLOB);
                sv[i][j] = ok ? sv[i][j] * SCALE : -INFINITY;
            }
        }

        // online softmax rows (reduce over tx: 16-lane groups)
#pragma unroll
        for (int i = 0; i < 4; i++) {
            float mx = fmaxf(fmaxf(sv[i][0], sv[i][1]), fmaxf(sv[i][2], sv[i][3]));
            mx = fmaxf(mx, __shfl_xor_sync(0xffffffffu, mx, 8, 16));
            mx = fmaxf(mx, __shfl_xor_sync(0xffffffffu, mx, 4, 16));
            mx = fmaxf(mx, __shfl_xor_sync(0xffffffffu, mx, 2, 16));
            mx = fmaxf(mx, __shfl_xor_sync(0xffffffffu, mx, 1, 16));

            float mnew = fmaxf(m[i], mx);
            float corr = __expf(m[i] - mnew);
            float rs = 0.0f;
#pragma unroll
            for (int j = 0; j < 4; j++) {
                float p = __expf(sv[i][j] - mnew);
                Ps[(ty4 + i) * PS_STRIDE + tx4 + j] = p;
                rs += p;
            }
            rs += __shfl_xor_sync(0xffffffffu, rs, 8, 16);
            rs += __shfl_xor_sync(0xffffffffu, rs, 4, 16);
            rs += __shfl_xor_sync(0xffffffffu, rs, 2, 16);
            rs += __shfl_xor_sync(0xffffffffu, rs, 1, 16);

            l[i] = l[i] * corr + rs;
            m[i] = mnew;
#pragma unroll
            for (int j = 0; j < 8; j++) acc[i][j] *= corr;
        }
        __syncthreads();

        // O += P @ V (4 rows x 8 cols per thread)
#pragma unroll 4
        for (int k = 0; k < 64; k++) {
            float v[8];
#pragma unroll
            for (int j = 0; j < 8; j++) v[j] = Vs[k * 128 + tx8 + j];
#pragma unroll
            for (int i = 0; i < 4; i++) {
                float p = Ps[(ty4 + i) * PS_STRIDE + k];
#pragma unroll
                for (int j = 0; j < 8; j++)
                    acc[i][j] = fmaf(p, v[j], acc[i][j]);
            }
        }
    }

    // epilogue: normalize and write to [seq][head*128 + d]
#pragma unroll
    for (int i = 0; i < 4; i++) {
        const float inv = 1.0f / l[i];
        float* dst = &O[(size_t)(q0 + ty4 + i) * HID + h * HD + tx8];
        *(float4*)&dst[0] = make_float4(acc[i][0] * inv, acc[i][1] * inv,
                                        acc[i][2] * inv, acc[i][3] * inv);
        *(float4*)&dst[4] = make_float4(acc[i][4] * inv, acc[i][5] * inv,
                                        acc[i][6] * inv, acc[i][7] * inv);
    }
}

// ---------------------------------------------------------------------------

extern "C" void kernel_launch(void* const* d_in, const int* in_sizes, int n_in,
                              void* d_out, int out_size)
{
    const float* X  = (const float*)d_in[0];
    const float* Wq = (const float*)d_in[1];
    const float* Wk = (const float*)d_in[2];
    const float* Wv = (const float*)d_in[3];
    const float* Wo = (const float*)d_in[4];
    float* out = (float*)d_out;

    float *q, *k, *v, *a;
    cudaGetSymbolAddress((void**)&q, g_Q);
    cudaGetSymbolAddress((void**)&k, g_K);
    cudaGetSymbolAddress((void**)&v, g_V);
    cudaGetSymbolAddress((void**)&a, g_A);

    cudaFuncSetAttribute(attn_kernel,
                         cudaFuncAttributeMaxDynamicSharedMemorySize, SMEM_BYTES);

    dim3 gg(HID / 128, SEQ / 128);
    gemm_kernel<<<gg, 256>>>(X, Wq, q, SEQ, HID, HID);
    gemm_kernel<<<gg, 256>>>(X, Wk, k, SEQ, HID, HID);
    gemm_kernel<<<gg, 256>>>(X, Wv, v, SEQ, HID, HID);

    attn_kernel<<<dim3(SEQ / 64, NH), 256, SMEM_BYTES>>>(q, k, v, a);

    gemm_kernel<<<gg, 256>>>(a, Wo, out, SEQ, HID, HID);
}

// round 9
// speedup vs baseline: 2.1656x; 2.1656x over previous
#include <cuda_runtime.h>
#include <cuda_bf16.h>
#include <math.h>
#include <stdint.h>

#define SEQ      4096
#define HID      2048
#define NH       16
#define HD       128
#define HALF_WIN 256
#define NGLOB    16
#define SCALE    0.08838834764831845f   // 128^-0.5

// GEMM tiling (mma.sync path)
#define KCH        32
#define NKCHUNK    (HID / KCH)       // 64
#define STAGE_B    32768             // Ah 8K | Al 8K | Bh 8K | Bl 8K
#define NSTAGES    3
#define GEMM_SMEM  (NSTAGES * STAGE_B)   // 98304

// Single dynamic-smem declaration shared by all kernels in this TU.
extern __shared__ __align__(1024) char dyn_smem[];

// ---------------------------------------------------------------------------
// Scratch (device globals: allocation-free rule)
// ---------------------------------------------------------------------------
__device__ float g_Q[SEQ * HID];
__device__ float g_K[SEQ * HID];
__device__ float g_V[SEQ * HID];
__device__ float g_A[SEQ * HID];

__device__ __nv_bfloat16 g_Xhi[SEQ * HID], g_Xlo[SEQ * HID];
__device__ __nv_bfloat16 g_AOhi[SEQ * HID], g_AOlo[SEQ * HID];
__device__ __nv_bfloat16 g_Wqhi[HID * HID], g_Wqlo[HID * HID];
__device__ __nv_bfloat16 g_Wkhi[HID * HID], g_Wklo[HID * HID];
__device__ __nv_bfloat16 g_Wvhi[HID * HID], g_Wvlo[HID * HID];
__device__ __nv_bfloat16 g_Wohi[HID * HID], g_Wolo[HID * HID];

// ---------------------------------------------------------------------------
// Helpers (sm_80-compatible PTX only: cp.async, ldmatrix, mma.sync)
// ---------------------------------------------------------------------------
__device__ __forceinline__ uint32_t smem_u32(const void* p) {
    uint32_t a;
    asm("{ .reg .u64 t; cvta.to.shared.u64 t, %1; cvt.u32.u64 %0, t; }" : "=r"(a) : "l"(p));
    return a;
}

__device__ __forceinline__ void cp16(uint32_t dst, const void* src) {
    asm volatile("cp.async.cg.shared.global [%0], [%1], 16;" :: "r"(dst), "l"(src));
}
#define CP_COMMIT() asm volatile("cp.async.commit_group;" ::: "memory")
#define CP_WAIT2()  asm volatile("cp.async.wait_group 2;" ::: "memory")

#define LDSM_X4(r0, r1, r2, r3, addr) \
    asm volatile("ldmatrix.sync.aligned.m8n8.x4.shared.b16 {%0,%1,%2,%3}, [%4];" \
                 : "=r"(r0), "=r"(r1), "=r"(r2), "=r"(r3) : "r"(addr))

#define LDSM_X4_T(r0, r1, r2, r3, addr) \
    asm volatile("ldmatrix.sync.aligned.m8n8.x4.trans.shared.b16 {%0,%1,%2,%3}, [%4];" \
                 : "=r"(r0), "=r"(r1), "=r"(r2), "=r"(r3) : "r"(addr))

#define MMA_BF16(d, a, b) \
    asm volatile("mma.sync.aligned.m16n8k16.row.col.f32.bf16.bf16.f32 " \
                 "{%0,%1,%2,%3}, {%4,%5,%6,%7}, {%8,%9}, {%0,%1,%2,%3};" \
                 : "+f"((d)[0]), "+f"((d)[1]), "+f"((d)[2]), "+f"((d)[3]) \
                 : "r"((a)[0]), "r"((a)[1]), "r"((a)[2]), "r"((a)[3]), \
                   "r"((b)[0]), "r"((b)[1]))

__device__ __forceinline__ uint32_t pack_bf2(__nv_bfloat16 a, __nv_bfloat16 b) {
    return (uint32_t)__bfloat16_as_ushort(a) | ((uint32_t)__bfloat16_as_ushort(b) << 16);
}

// ---------------------------------------------------------------------------
// Elementwise hi/lo split: fp32 -> bf16 hi + bf16 lo (x - hi), same layout.
// 4 elements/thread.
// ---------------------------------------------------------------------------
__global__ __launch_bounds__(256) void split_kernel(
    const float* __restrict__ X, __nv_bfloat16* __restrict__ hi,
    __nv_bfloat16* __restrict__ lo)
{
    size_t i = ((size_t)blockIdx.x * 256 + threadIdx.x) * 4;
    float4 x = *(const float4*)(X + i);
    float xs[4] = {x.x, x.y, x.z, x.w};
    __nv_bfloat16 h[4], l[4];
#pragma unroll
    for (int j = 0; j < 4; j++) {
        h[j] = __float2bfloat16_rn(xs[j]);
        l[j] = __float2bfloat16_rn(xs[j] - __bfloat162float(h[j]));
    }
    *(uint2*)(hi + i) = make_uint2(pack_bf2(h[0], h[1]), pack_bf2(h[2], h[3]));
    *(uint2*)(lo + i) = make_uint2(pack_bf2(l[0], l[1]), pack_bf2(l[2], l[3]));
}

// ---------------------------------------------------------------------------
// cp.async chunk loader: A [128 rows][32 k] (64B rows, 4x16B units, XOR key
// (r>>1)&3), B [32 k][128 n] (256B rows, 16x16B units, XOR key r&7).
// ---------------------------------------------------------------------------
__device__ __forceinline__ void load_chunk(
    uint32_t sbase,
    const __nv_bfloat16* __restrict__ Ahi, const __nv_bfloat16* __restrict__ Alo,
    const __nv_bfloat16* __restrict__ Bhi, const __nv_bfloat16* __restrict__ Blo,
    int mtile, int ntile, int kc, int tid)
{
#pragma unroll
    for (int i = 0; i < 2; i++) {
        int unit = tid + i * 256;                 // 0..511
        int r = unit >> 2, u = unit & 3;
        uint32_t dst = sbase + r * 64 + ((u ^ ((r >> 1) & 3)) << 4);
        size_t g = (size_t)(mtile * 128 + r) * HID + kc * KCH + u * 8;
        cp16(dst,        Ahi + g);
        cp16(dst + 8192, Alo + g);
    }
#pragma unroll
    for (int i = 0; i < 2; i++) {
        int unit = tid + i * 256;
        int r = unit >> 4, u = unit & 15;
        uint32_t dst = sbase + 16384 + r * 256 + ((u ^ (r & 7)) << 4);
        size_t g = (size_t)(kc * KCH + r) * HID + ntile * 128 + u * 8;
        cp16(dst,        Bhi + g);
        cp16(dst + 8192, Blo + g);
    }
}

// ---------------------------------------------------------------------------
// bf16 mma.sync GEMM with 3-term hi/lo compensation.
// C[4096][2048] = (Ahi+Alo) @ (Bhi+Blo), A row-major [M][K], B row-major [K][N].
// CTA 128x128, 8 warps (warp tile 64x32), K-chunk 32, 3-stage cp.async pipe.
// ---------------------------------------------------------------------------
__global__ __launch_bounds__(256, 2) void gemm_mma_kernel(
    const __nv_bfloat16* __restrict__ Ahi, const __nv_bfloat16* __restrict__ Alo,
    const __nv_bfloat16* __restrict__ Bhi, const __nv_bfloat16* __restrict__ Blo,
    float* __restrict__ C)
{
    const uint32_t sb = smem_u32(dyn_smem);
    const int tid  = threadIdx.x;
    const int lane = tid & 31;
    const int wid  = tid >> 5;
    const int ntile = blockIdx.x;
    const int mtile = blockIdx.y;
    const int wm = (wid & 1) * 64;
    const int wn = (wid >> 1) * 32;

    float acc[4][4][4];
#pragma unroll
    for (int a = 0; a < 4; a++)
#pragma unroll
        for (int b = 0; b < 4; b++)
#pragma unroll
            for (int c = 0; c < 4; c++) acc[a][b][c] = 0.0f;

    // prefetch chunks 0..2
#pragma unroll
    for (int s = 0; s < NSTAGES; s++) {
        load_chunk(sb + s * STAGE_B, Ahi, Alo, Bhi, Blo, mtile, ntile, s, tid);
        CP_COMMIT();
    }

    for (int c = 0; c < NKCHUNK; c++) {
        const int s = c % NSTAGES;
        const uint32_t sA  = sb + s * STAGE_B;
        const uint32_t sBh = sA + 16384;

        CP_WAIT2();
        __syncthreads();

#pragma unroll
        for (int ks = 0; ks < KCH; ks += 16) {
            uint32_t ah[4][4], bh[4][2], bl[4][2];

            // B fragments (hi+lo), 2 ldmatrix.x4.trans per term cover 4 n-tiles
            const int brow = ks + (lane & 7) + ((lane >> 3) & 1) * 8;
            const int bnh  = (lane >> 4) * 8;
#pragma unroll
            for (int p = 0; p < 2; p++) {
                const int ncol = wn + p * 16 + bnh;
                uint32_t addr = sBh + brow * 256 + (((ncol >> 3) ^ (brow & 7)) << 4);
                uint32_t r0, r1, r2, r3;
                LDSM_X4_T(r0, r1, r2, r3, addr);
                bh[2 * p][0] = r0; bh[2 * p][1] = r1;
                bh[2 * p + 1][0] = r2; bh[2 * p + 1][1] = r3;
                LDSM_X4_T(r0, r1, r2, r3, addr + 8192);
                bl[2 * p][0] = r0; bl[2 * p][1] = r1;
                bl[2 * p + 1][0] = r2; bl[2 * p + 1][1] = r3;
            }

            // A hi fragments
            const int au = (ks >> 3) + (lane >> 4);
#pragma unroll
            for (int mi = 0; mi < 4; mi++) {
                const int m = wm + mi * 16 + (lane & 15);
                uint32_t addr = sA + m * 64 + ((au ^ ((m >> 1) & 3)) << 4);
                LDSM_X4(ah[mi][0], ah[mi][1], ah[mi][2], ah[mi][3], addr);
            }
            // hi*hi + hi*lo
#pragma unroll
            for (int mi = 0; mi < 4; mi++)
#pragma unroll
                for (int ni = 0; ni < 4; ni++) {
                    MMA_BF16(acc[mi][ni], ah[mi], bh[ni]);
                    MMA_BF16(acc[mi][ni], ah[mi], bl[ni]);
                }
            // A lo fragments (reuse regs) + lo*hi
#pragma unroll
            for (int mi = 0; mi < 4; mi++) {
                const int m = wm + mi * 16 + (lane & 15);
                uint32_t addr = sA + 8192 + m * 64 + ((au ^ ((m >> 1) & 3)) << 4);
                LDSM_X4(ah[mi][0], ah[mi][1], ah[mi][2], ah[mi][3], addr);
            }
#pragma unroll
            for (int mi = 0; mi < 4; mi++)
#pragma unroll
                for (int ni = 0; ni < 4; ni++)
                    MMA_BF16(acc[mi][ni], ah[mi], bh[ni]);
        }

        __syncthreads();
        const int cn = c + NSTAGES;
        if (cn < NKCHUNK)
            load_chunk(sb + s * STAGE_B, Ahi, Alo, Bhi, Blo, mtile, ntile, cn, tid);
        CP_COMMIT();
    }

    // epilogue
    float* Cb = C + (size_t)(mtile * 128) * HID + ntile * 128;
#pragma unroll
    for (int mi = 0; mi < 4; mi++) {
#pragma unroll
        for (int ni = 0; ni < 4; ni++) {
            const int r0  = wm + mi * 16 + (lane >> 2);
            const int col = wn + ni * 8 + (lane & 3) * 2;
            *(float2*)&Cb[(size_t)r0 * HID + col] =
                make_float2(acc[mi][ni][0], acc[mi][ni][1]);
            *(float2*)&Cb[(size_t)(r0 + 8) * HID + col] =
                make_float2(acc[mi][ni][2], acc[mi][ni][3]);
        }
    }
}

// ---------------------------------------------------------------------------
// Flash-attention (unchanged fp32 SIMT baseline)
// ---------------------------------------------------------------------------
#define QS_STRIDE 129
#define PS_STRIDE 65
#define SMEM_FLOATS (64 * QS_STRIDE * 2 + 64 * 128 + 64 * PS_STRIDE)
#define SMEM_BYTES  (SMEM_FLOATS * 4)

__global__ __launch_bounds__(256) void attn_kernel(
    const float* __restrict__ Q, const float* __restrict__ K,
    const float* __restrict__ V, float* __restrict__ O)
{
    float* smem = (float*)dyn_smem;
    float* Qs = smem;
    float* Ks = Qs + 64 * QS_STRIDE;
    float* Vs = Ks + 64 * QS_STRIDE;
    float* Ps = Vs + 64 * 128;

    const int tid = threadIdx.x;
    const int ty  = tid >> 4;
    const int tx  = tid & 15;
    const int ty4 = ty * 4;
    const int tx4 = tx * 4;
    const int tx8 = tx * 8;
    const int q0  = blockIdx.x * 64;
    const int h   = blockIdx.y;

    for (int s = tid; s < 64 * 32; s += 256) {
        int r  = s >> 5;
        int c4 = (s & 31) << 2;
        float4 v = *(const float4*)&Q[(size_t)(q0 + r) * HID + h * HD + c4];
        float* d = &Qs[r * QS_STRIDE + c4];
        d[0] = v.x; d[1] = v.y; d[2] = v.z; d[3] = v.w;
    }

    float m[4], l[4], acc[4][8];
#pragma unroll
    for (int i = 0; i < 4; i++) {
        m[i] = -INFINITY;
        l[i] = 0.0f;
#pragma unroll
        for (int j = 0; j < 8; j++) acc[i][j] = 0.0f;
    }

    int t_lo, t_hi;
    if (q0 == 0) {
        t_lo = 1; t_hi = 63;
    } else {
        int lo = q0 - (HALF_WIN - 1);
        t_lo = (lo < 64) ? 1 : (lo >> 6);
        t_hi = (q0 + 63 + HALF_WIN - 1) >> 6;
        if (t_hi > 63) t_hi = 63;
    }

    for (int it = -1;; it++) {
        int t;
        if (it < 0) t = 0;
        else { t = t_lo + it; if (t > t_hi) break; }
        const int kv0 = t << 6;

        __syncthreads();
        for (int s = tid; s < 64 * 32; s += 256) {
            int r  = s >> 5;
            int c4 = (s & 31) << 2;
            float4 kv = *(const float4*)&K[(size_t)(kv0 + r) * HID + h * HD + c4];
            float* kd = &Ks[r * QS_STRIDE + c4];
            kd[0] = kv.x; kd[1] = kv.y; kd[2] = kv.z; kd[3] = kv.w;
            float4 vv = *(const float4*)&V[(size_t)(kv0 + r) * HID + h * HD + c4];
            *(float4*)&Vs[r * 128 + c4] = vv;
        }
        __syncthreads();

        float sv[4][4];
#pragma unroll
        for (int i = 0; i < 4; i++)
#pragma unroll
            for (int j = 0; j < 4; j++) sv[i][j] = 0.0f;

#pragma unroll 8
        for (int k = 0; k < 128; k++) {
            float a[4], b[4];
#pragma unroll
            for (int i = 0; i < 4; i++) a[i] = Qs[(ty4 + i) * QS_STRIDE + k];
#pragma unroll
            for (int j = 0; j < 4; j++) b[j] = Ks[(tx4 + j) * QS_STRIDE + k];
#pragma unroll
            for (int i = 0; i < 4; i++)
#pragma unroll
                for (int j = 0; j < 4; j++)
                    sv[i][j] = fmaf(a[i], b[j], sv[i][j]);
        }

#pragma unroll
        for (int i = 0; i < 4; i++) {
            const int qi = q0 + ty4 + i;
#pragma unroll
            for (int j = 0; j < 4; j++) {
                const int kj = kv0 + tx4 + j;
                const int d  = qi - kj;
                const bool ok = (d < HALF_WIN && d > -HALF_WIN) || (qi < NGLOB) || (kj < NGLOB);
                sv[i][j] = ok ? sv[i][j] * SCALE : -INFINITY;
            }
        }

#pragma unroll
        for (int i = 0; i < 4; i++) {
            float mx = fmaxf(fmaxf(sv[i][0], sv[i][1]), fmaxf(sv[i][2], sv[i][3]));
            mx = fmaxf(mx, __shfl_xor_sync(0xffffffffu, mx, 8, 16));
            mx = fmaxf(mx, __shfl_xor_sync(0xffffffffu, mx, 4, 16));
            mx = fmaxf(mx, __shfl_xor_sync(0xffffffffu, mx, 2, 16));
            mx = fmaxf(mx, __shfl_xor_sync(0xffffffffu, mx, 1, 16));

            float mnew = fmaxf(m[i], mx);
            float corr = __expf(m[i] - mnew);
            float rs = 0.0f;
#pragma unroll
            for (int j = 0; j < 4; j++) {
                float p = __expf(sv[i][j] - mnew);
                Ps[(ty4 + i) * PS_STRIDE + tx4 + j] = p;
                rs += p;
            }
            rs += __shfl_xor_sync(0xffffffffu, rs, 8, 16);
            rs += __shfl_xor_sync(0xffffffffu, rs, 4, 16);
            rs += __shfl_xor_sync(0xffffffffu, rs, 2, 16);
            rs += __shfl_xor_sync(0xffffffffu, rs, 1, 16);

            l[i] = l[i] * corr + rs;
            m[i] = mnew;
#pragma unroll
            for (int j = 0; j < 8; j++) acc[i][j] *= corr;
        }
        __syncthreads();

#pragma unroll 4
        for (int k = 0; k < 64; k++) {
            float v[8];
#pragma unroll
            for (int j = 0; j < 8; j++) v[j] = Vs[k * 128 + tx8 + j];
#pragma unroll
            for (int i = 0; i < 4; i++) {
                float p = Ps[(ty4 + i) * PS_STRIDE + k];
#pragma unroll
                for (int j = 0; j < 8; j++)
                    acc[i][j] = fmaf(p, v[j], acc[i][j]);
            }
        }
    }

#pragma unroll
    for (int i = 0; i < 4; i++) {
        const float inv = 1.0f / l[i];
        float* dst = &O[(size_t)(q0 + ty4 + i) * HID + h * HD + tx8];
        *(float4*)&dst[0] = make_float4(acc[i][0] * inv, acc[i][1] * inv,
                                        acc[i][2] * inv, acc[i][3] * inv);
        *(float4*)&dst[4] = make_float4(acc[i][4] * inv, acc[i][5] * inv,
                                        acc[i][6] * inv, acc[i][7] * inv);
    }
}

// ---------------------------------------------------------------------------

extern "C" void kernel_launch(void* const* d_in, const int* in_sizes, int n_in,
                              void* d_out, int out_size)
{
    const float* X  = (const float*)d_in[0];
    const float* Wq = (const float*)d_in[1];
    const float* Wk = (const float*)d_in[2];
    const float* Wv = (const float*)d_in[3];
    const float* Wo = (const float*)d_in[4];
    float* out = (float*)d_out;

    float *q, *k, *v, *a;
    cudaGetSymbolAddress((void**)&q, g_Q);
    cudaGetSymbolAddress((void**)&k, g_K);
    cudaGetSymbolAddress((void**)&v, g_V);
    cudaGetSymbolAddress((void**)&a, g_A);

    __nv_bfloat16 *xhi, *xlo, *aohi, *aolo;
    __nv_bfloat16 *wqh, *wql, *wkh, *wkl, *wvh, *wvl, *woh, *wol;
    cudaGetSymbolAddress((void**)&xhi, g_Xhi);
    cudaGetSymbolAddress((void**)&xlo, g_Xlo);
    cudaGetSymbolAddress((void**)&aohi, g_AOhi);
    cudaGetSymbolAddress((void**)&aolo, g_AOlo);
    cudaGetSymbolAddress((void**)&wqh, g_Wqhi);
    cudaGetSymbolAddress((void**)&wql, g_Wqlo);
    cudaGetSymbolAddress((void**)&wkh, g_Wkhi);
    cudaGetSymbolAddress((void**)&wkl, g_Wklo);
    cudaGetSymbolAddress((void**)&wvh, g_Wvhi);
    cudaGetSymbolAddress((void**)&wvl, g_Wvlo);
    cudaGetSymbolAddress((void**)&woh, g_Wohi);
    cudaGetSymbolAddress((void**)&wol, g_Wolo);

    cudaFuncSetAttribute(attn_kernel,
                         cudaFuncAttributeMaxDynamicSharedMemorySize, SMEM_BYTES);
    cudaFuncSetAttribute(gemm_mma_kernel,
                         cudaFuncAttributeMaxDynamicSharedMemorySize, GEMM_SMEM);

    const int xblocks = SEQ * HID / 4 / 256;   // 8192
    const int wblocks = HID * HID / 4 / 256;   // 4096
    dim3 gg(HID / 128, SEQ / 128);             // (16, 32)

    split_kernel<<<xblocks, 256>>>(X, xhi, xlo);
    split_kernel<<<wblocks, 256>>>(Wq, wqh, wql);
    split_kernel<<<wblocks, 256>>>(Wk, wkh, wkl);
    split_kernel<<<wblocks, 256>>>(Wv, wvh, wvl);
    split_kernel<<<wblocks, 256>>>(Wo, woh, wol);

    gemm_mma_kernel<<<gg, 256, GEMM_SMEM>>>(xhi, xlo, wqh, wql, q);
    gemm_mma_kernel<<<gg, 256, GEMM_SMEM>>>(xhi, xlo, wkh, wkl, k);
    gemm_mma_kernel<<<gg, 256, GEMM_SMEM>>>(xhi, xlo, wvh, wvl, v);

    attn_kernel<<<dim3(SEQ / 64, NH), 256, SMEM_BYTES>>>(q, k, v, a);

    split_kernel<<<xblocks, 256>>>(a, aohi, aolo);
    gemm_mma_kernel<<<gg, 256, GEMM_SMEM>>>(aohi, aolo, woh, wol, out);
}

// round 10
// speedup vs baseline: 3.6676x; 1.6935x over previous
#include <cuda_runtime.h>
#include <cuda_bf16.h>
#include <math.h>
#include <stdint.h>

#define SEQ      4096
#define HID      2048
#define NH       16
#define HD       128
#define HALF_WIN 256
#define NGLOB    16
#define SCALE    0.08838834764831845f   // 128^-0.5

// GEMM tiling (mma.sync path)
#define KCH        32
#define NKCHUNK    (HID / KCH)       // 64
#define STAGE_B    32768             // Ah 8K | Al 8K | Bh 8K | Bl 8K
#define NSTAGES    3
#define GEMM_SMEM  (NSTAGES * STAGE_B)   // 98304

// Attention smem: Qhi 32K | Qlo 32K | 2 KV stages (Khi|Klo|Vhi|Vlo = 64K each)
#define ATTN_SMEM  (65536 + 2 * 65536)   // 196608

// Single dynamic-smem declaration shared by all kernels in this TU.
extern __shared__ __align__(1024) char dyn_smem[];

// ---------------------------------------------------------------------------
// Scratch (device globals: allocation-free rule)
// ---------------------------------------------------------------------------
__device__ __nv_bfloat16 g_Xhi[SEQ * HID], g_Xlo[SEQ * HID];
__device__ __nv_bfloat16 g_Qhi[SEQ * HID], g_Qlo[SEQ * HID];
__device__ __nv_bfloat16 g_Khi[SEQ * HID], g_Klo[SEQ * HID];
__device__ __nv_bfloat16 g_Vhi[SEQ * HID], g_Vlo[SEQ * HID];
__device__ __nv_bfloat16 g_AOhi[SEQ * HID], g_AOlo[SEQ * HID];
__device__ __nv_bfloat16 g_Wqhi[HID * HID], g_Wqlo[HID * HID];
__device__ __nv_bfloat16 g_Wkhi[HID * HID], g_Wklo[HID * HID];
__device__ __nv_bfloat16 g_Wvhi[HID * HID], g_Wvlo[HID * HID];
__device__ __nv_bfloat16 g_Wohi[HID * HID], g_Wolo[HID * HID];

// ---------------------------------------------------------------------------
// Helpers (sm_80-compatible PTX only: cp.async, ldmatrix, mma.sync)
// ---------------------------------------------------------------------------
__device__ __forceinline__ uint32_t smem_u32(const void* p) {
    uint32_t a;
    asm("{ .reg .u64 t; cvta.to.shared.u64 t, %1; cvt.u32.u64 %0, t; }" : "=r"(a) : "l"(p));
    return a;
}

__device__ __forceinline__ void cp16(uint32_t dst, const void* src) {
    asm volatile("cp.async.cg.shared.global [%0], [%1], 16;" :: "r"(dst), "l"(src));
}
#define CP_COMMIT() asm volatile("cp.async.commit_group;" ::: "memory")
#define CP_WAIT2()  asm volatile("cp.async.wait_group 2;" ::: "memory")
#define CP_WAIT1()  asm volatile("cp.async.wait_group 1;" ::: "memory")

#define LDSM_X4(r0, r1, r2, r3, addr) \
    asm volatile("ldmatrix.sync.aligned.m8n8.x4.shared.b16 {%0,%1,%2,%3}, [%4];" \
                 : "=r"(r0), "=r"(r1), "=r"(r2), "=r"(r3) : "r"(addr))

#define LDSM_X4_T(r0, r1, r2, r3, addr) \
    asm volatile("ldmatrix.sync.aligned.m8n8.x4.trans.shared.b16 {%0,%1,%2,%3}, [%4];" \
                 : "=r"(r0), "=r"(r1), "=r"(r2), "=r"(r3) : "r"(addr))

#define MMA_BF16(d, a, b) \
    asm volatile("mma.sync.aligned.m16n8k16.row.col.f32.bf16.bf16.f32 " \
                 "{%0,%1,%2,%3}, {%4,%5,%6,%7}, {%8,%9}, {%0,%1,%2,%3};" \
                 : "+f"((d)[0]), "+f"((d)[1]), "+f"((d)[2]), "+f"((d)[3]) \
                 : "r"((a)[0]), "r"((a)[1]), "r"((a)[2]), "r"((a)[3]), \
                   "r"((b)[0]), "r"((b)[1]))

__device__ __forceinline__ uint32_t pack_bf2(__nv_bfloat16 a, __nv_bfloat16 b) {
    return (uint32_t)__bfloat16_as_ushort(a) | ((uint32_t)__bfloat16_as_ushort(b) << 16);
}
__device__ __forceinline__ uint32_t pack_hi(float x, float y) {
    return pack_bf2(__float2bfloat16_rn(x), __float2bfloat16_rn(y));
}
__device__ __forceinline__ uint32_t pack_lo(float x, float y) {
    __nv_bfloat16 hx = __float2bfloat16_rn(x), hy = __float2bfloat16_rn(y);
    return pack_bf2(__float2bfloat16_rn(x - __bfloat162float(hx)),
                    __float2bfloat16_rn(y - __bfloat162float(hy)));
}

// ---------------------------------------------------------------------------
// Elementwise hi/lo split: fp32 -> bf16 hi + bf16 lo (x - hi), same layout.
// ---------------------------------------------------------------------------
__global__ __launch_bounds__(256) void split_kernel(
    const float* __restrict__ X, __nv_bfloat16* __restrict__ hi,
    __nv_bfloat16* __restrict__ lo)
{
    size_t i = ((size_t)blockIdx.x * 256 + threadIdx.x) * 4;
    float4 x = *(const float4*)(X + i);
    float xs[4] = {x.x, x.y, x.z, x.w};
    __nv_bfloat16 h[4], l[4];
#pragma unroll
    for (int j = 0; j < 4; j++) {
        h[j] = __float2bfloat16_rn(xs[j]);
        l[j] = __float2bfloat16_rn(xs[j] - __bfloat162float(h[j]));
    }
    *(uint2*)(hi + i) = make_uint2(pack_bf2(h[0], h[1]), pack_bf2(h[2], h[3]));
    *(uint2*)(lo + i) = make_uint2(pack_bf2(l[0], l[1]), pack_bf2(l[2], l[3]));
}

// ---------------------------------------------------------------------------
// GEMM chunk loader (unchanged from R9)
// ---------------------------------------------------------------------------
__device__ __forceinline__ void load_chunk(
    uint32_t sbase,
    const __nv_bfloat16* __restrict__ Ahi, const __nv_bfloat16* __restrict__ Alo,
    const __nv_bfloat16* __restrict__ Bhi, const __nv_bfloat16* __restrict__ Blo,
    int mtile, int ntile, int kc, int tid)
{
#pragma unroll
    for (int i = 0; i < 2; i++) {
        int unit = tid + i * 256;
        int r = unit >> 2, u = unit & 3;
        uint32_t dst = sbase + r * 64 + ((u ^ ((r >> 1) & 3)) << 4);
        size_t g = (size_t)(mtile * 128 + r) * HID + kc * KCH + u * 8;
        cp16(dst,        Ahi + g);
        cp16(dst + 8192, Alo + g);
    }
#pragma unroll
    for (int i = 0; i < 2; i++) {
        int unit = tid + i * 256;
        int r = unit >> 4, u = unit & 15;
        uint32_t dst = sbase + 16384 + r * 256 + ((u ^ (r & 7)) << 4);
        size_t g = (size_t)(kc * KCH + r) * HID + ntile * 128 + u * 8;
        cp16(dst,        Bhi + g);
        cp16(dst + 8192, Blo + g);
    }
}

// ---------------------------------------------------------------------------
// bf16 mma.sync GEMM with 3-term hi/lo compensation.
// SPLIT=true: write bf16 hi/lo outputs; SPLIT=false: write fp32 C.
// ---------------------------------------------------------------------------
template<bool SPLIT>
__global__ __launch_bounds__(256, 2) void gemm_mma_kernel(
    const __nv_bfloat16* __restrict__ Ahi, const __nv_bfloat16* __restrict__ Alo,
    const __nv_bfloat16* __restrict__ Bhi, const __nv_bfloat16* __restrict__ Blo,
    float* __restrict__ C,
    __nv_bfloat16* __restrict__ Ohi, __nv_bfloat16* __restrict__ Olo)
{
    const uint32_t sb = smem_u32(dyn_smem);
    const int tid  = threadIdx.x;
    const int lane = tid & 31;
    const int wid  = tid >> 5;
    const int ntile = blockIdx.x;
    const int mtile = blockIdx.y;
    const int wm = (wid & 1) * 64;
    const int wn = (wid >> 1) * 32;

    float acc[4][4][4];
#pragma unroll
    for (int a = 0; a < 4; a++)
#pragma unroll
        for (int b = 0; b < 4; b++)
#pragma unroll
            for (int c = 0; c < 4; c++) acc[a][b][c] = 0.0f;

#pragma unroll
    for (int s = 0; s < NSTAGES; s++) {
        load_chunk(sb + s * STAGE_B, Ahi, Alo, Bhi, Blo, mtile, ntile, s, tid);
        CP_COMMIT();
    }

    for (int c = 0; c < NKCHUNK; c++) {
        const int s = c % NSTAGES;
        const uint32_t sA  = sb + s * STAGE_B;
        const uint32_t sBh = sA + 16384;

        CP_WAIT2();
        __syncthreads();

#pragma unroll
        for (int ks = 0; ks < KCH; ks += 16) {
            uint32_t ah[4][4], bh[4][2], bl[4][2];

            const int brow = ks + (lane & 7) + ((lane >> 3) & 1) * 8;
            const int bnh  = (lane >> 4) * 8;
#pragma unroll
            for (int p = 0; p < 2; p++) {
                const int ncol = wn + p * 16 + bnh;
                uint32_t addr = sBh + brow * 256 + (((ncol >> 3) ^ (brow & 7)) << 4);
                uint32_t r0, r1, r2, r3;
                LDSM_X4_T(r0, r1, r2, r3, addr);
                bh[2 * p][0] = r0; bh[2 * p][1] = r1;
                bh[2 * p + 1][0] = r2; bh[2 * p + 1][1] = r3;
                LDSM_X4_T(r0, r1, r2, r3, addr + 8192);
                bl[2 * p][0] = r0; bl[2 * p][1] = r1;
                bl[2 * p + 1][0] = r2; bl[2 * p + 1][1] = r3;
            }

            const int au = (ks >> 3) + (lane >> 4);
#pragma unroll
            for (int mi = 0; mi < 4; mi++) {
                const int m = wm + mi * 16 + (lane & 15);
                uint32_t addr = sA + m * 64 + ((au ^ ((m >> 1) & 3)) << 4);
                LDSM_X4(ah[mi][0], ah[mi][1], ah[mi][2], ah[mi][3], addr);
            }
#pragma unroll
            for (int mi = 0; mi < 4; mi++)
#pragma unroll
                for (int ni = 0; ni < 4; ni++) {
                    MMA_BF16(acc[mi][ni], ah[mi], bh[ni]);
                    MMA_BF16(acc[mi][ni], ah[mi], bl[ni]);
                }
#pragma unroll
            for (int mi = 0; mi < 4; mi++) {
                const int m = wm + mi * 16 + (lane & 15);
                uint32_t addr = sA + 8192 + m * 64 + ((au ^ ((m >> 1) & 3)) << 4);
                LDSM_X4(ah[mi][0], ah[mi][1], ah[mi][2], ah[mi][3], addr);
            }
#pragma unroll
            for (int mi = 0; mi < 4; mi++)
#pragma unroll
                for (int ni = 0; ni < 4; ni++)
                    MMA_BF16(acc[mi][ni], ah[mi], bh[ni]);
        }

        __syncthreads();
        const int cn = c + NSTAGES;
        if (cn < NKCHUNK)
            load_chunk(sb + s * STAGE_B, Ahi, Alo, Bhi, Blo, mtile, ntile, cn, tid);
        CP_COMMIT();
    }

    const size_t cbase = (size_t)(mtile * 128) * HID + ntile * 128;
#pragma unroll
    for (int mi = 0; mi < 4; mi++) {
#pragma unroll
        for (int ni = 0; ni < 4; ni++) {
            const int r0  = wm + mi * 16 + (lane >> 2);
            const int col = wn + ni * 8 + (lane & 3) * 2;
            const size_t i0 = cbase + (size_t)r0 * HID + col;
            const size_t i1 = i0 + 8 * HID;
            if (SPLIT) {
                *(uint32_t*)&Ohi[i0] = pack_hi(acc[mi][ni][0], acc[mi][ni][1]);
                *(uint32_t*)&Olo[i0] = pack_lo(acc[mi][ni][0], acc[mi][ni][1]);
                *(uint32_t*)&Ohi[i1] = pack_hi(acc[mi][ni][2], acc[mi][ni][3]);
                *(uint32_t*)&Olo[i1] = pack_lo(acc[mi][ni][2], acc[mi][ni][3]);
            } else {
                *(float2*)&C[i0] = make_float2(acc[mi][ni][0], acc[mi][ni][1]);
                *(float2*)&C[i1] = make_float2(acc[mi][ni][2], acc[mi][ni][3]);
            }
        }
    }
}

// ---------------------------------------------------------------------------
// Flash attention, mma.sync bf16 with hi/lo compensation.
// Block: 128 queries x 1 head, 256 threads (8 warps, 16 q rows each).
// KV tiles of 64 keys, double-buffered cp.async.
// ---------------------------------------------------------------------------
__device__ __forceinline__ void attn_load_kv(
    uint32_t kvb, int t, int tid, int h,
    const __nv_bfloat16* __restrict__ Khi, const __nv_bfloat16* __restrict__ Klo,
    const __nv_bfloat16* __restrict__ Vhi, const __nv_bfloat16* __restrict__ Vlo)
{
#pragma unroll
    for (int i = 0; i < 4; i++) {
        int u = tid + 256 * i;
        int r = u >> 4, c = u & 15;
        size_t g = (size_t)(t * 64 + r) * HID + h * HD + c * 8;
        uint32_t dst = kvb + r * 256 + ((c ^ (r & 7)) << 4);
        cp16(dst,         Khi + g);
        cp16(dst + 16384, Klo + g);
        cp16(dst + 32768, Vhi + g);
        cp16(dst + 49152, Vlo + g);
    }
}

__global__ __launch_bounds__(256, 1) void attn_mma_kernel(
    const __nv_bfloat16* __restrict__ Qhi, const __nv_bfloat16* __restrict__ Qlo,
    const __nv_bfloat16* __restrict__ Khi, const __nv_bfloat16* __restrict__ Klo,
    const __nv_bfloat16* __restrict__ Vhi, const __nv_bfloat16* __restrict__ Vlo,
    __nv_bfloat16* __restrict__ Ohi, __nv_bfloat16* __restrict__ Olo)
{
    const uint32_t sb = smem_u32(dyn_smem);
    const uint32_t SQ = sb;                     // Qhi 32K, Qlo at +32768
    const int tid = threadIdx.x, lane = tid & 31, wid = tid >> 5;
    const int wm = wid * 16;
    const int q0 = blockIdx.x * 128;
    const int h  = blockIdx.y;
    const int lr = lane & 15, lc = (lane >> 4) * 8;

    // Q tile load (hi+lo), own commit group
#pragma unroll
    for (int i = 0; i < 8; i++) {
        int u = tid + 256 * i;
        int r = u >> 4, c = u & 15;
        size_t g = (size_t)(q0 + r) * HID + h * HD + c * 8;
        uint32_t dst = SQ + r * 256 + ((c ^ (r & 7)) << 4);
        cp16(dst,         Qhi + g);
        cp16(dst + 32768, Qlo + g);
    }
    CP_COMMIT();

    int t_lo, t_hi;
    if (q0 == 0) { t_lo = 1; t_hi = 63; }
    else {
        int lo = q0 - (HALF_WIN - 1);
        t_lo = (lo < 64) ? 1 : (lo >> 6);
        t_hi = (q0 + 127 + HALF_WIN - 1) >> 6;
        if (t_hi > 63) t_hi = 63;
    }
    const int n_tiles = t_hi - t_lo + 2;   // tile(0)=0 (globals), then t_lo..t_hi

    attn_load_kv(sb + 65536, 0, tid, h, Khi, Klo, Vhi, Vlo);
    CP_COMMIT();

    float m0 = -INFINITY, m1 = -INFINITY, l0 = 0.0f, l1 = 0.0f;
    float ov[16][4];
#pragma unroll
    for (int n = 0; n < 16; n++)
#pragma unroll
        for (int c = 0; c < 4; c++) ov[n][c] = 0.0f;

    const int r0g = q0 + wm + (lane >> 2);
    const int r1g = r0g + 8;

    for (int it = 0; it < n_tiles; it++) {
        const int s = it & 1;
        const uint32_t kvb = sb + 65536 + s * 65536;

        __syncthreads();               // prev compute done before stage reuse
        if (it + 1 < n_tiles)
            attn_load_kv(sb + 65536 + (s ^ 1) * 65536, t_lo + it, tid, h,
                         Khi, Klo, Vhi, Vlo);
        CP_COMMIT();
        CP_WAIT1();
        __syncthreads();               // current tile visible to all threads

        const int t   = (it == 0) ? 0 : (t_lo + it - 1);
        const int kv0 = t << 6;

        // ---- S = Q K^T (3-term) ----
        float sv[8][4];
#pragma unroll
        for (int j = 0; j < 8; j++)
#pragma unroll
            for (int c = 0; c < 4; c++) sv[j][c] = 0.0f;

#pragma unroll
        for (int ks = 0; ks < 8; ks++) {
            uint32_t qh[4], ql[4];
            {
                int r = wm + lr, d = 16 * ks + lc;
                uint32_t a = SQ + r * 256 + (((d >> 3) ^ (r & 7)) << 4);
                LDSM_X4(qh[0], qh[1], qh[2], qh[3], a);
                LDSM_X4(ql[0], ql[1], ql[2], ql[3], a + 32768);
            }
#pragma unroll
            for (int j4 = 0; j4 < 4; j4++) {
                uint32_t kh[4], kl[4];
                int r = 16 * j4 + lr, d = 16 * ks + lc;
                uint32_t a = kvb + r * 256 + (((d >> 3) ^ (r & 7)) << 4);
                LDSM_X4(kh[0], kh[1], kh[2], kh[3], a);
                LDSM_X4(kl[0], kl[1], kl[2], kl[3], a + 16384);
                uint32_t b0[2] = {kh[0], kh[2]}, b1[2] = {kh[1], kh[3]};
                uint32_t c0[2] = {kl[0], kl[2]}, c1[2] = {kl[1], kl[3]};
                MMA_BF16(sv[2 * j4],     qh, b0);
                MMA_BF16(sv[2 * j4],     qh, c0);
                MMA_BF16(sv[2 * j4],     ql, b0);
                MMA_BF16(sv[2 * j4 + 1], qh, b1);
                MMA_BF16(sv[2 * j4 + 1], qh, c1);
                MMA_BF16(sv[2 * j4 + 1], ql, b1);
            }
        }

        // ---- scale + mask ----
#pragma unroll
        for (int j = 0; j < 8; j++) {
            const int kc = kv0 + 8 * j + (lane & 3) * 2;
#pragma unroll
            for (int c = 0; c < 4; c++) {
                const int qi = (c < 2) ? r0g : r1g;
                const int kj = kc + (c & 1);
                const int d  = qi - kj;
                const bool ok = (d < HALF_WIN && d > -HALF_WIN) ||
                                (qi < NGLOB) || (kj < NGLOB);
                sv[j][c] = ok ? sv[j][c] * SCALE : -INFINITY;
            }
        }

        // ---- online softmax (2 rows per thread) ----
        float mx0 = -INFINITY, mx1 = -INFINITY;
#pragma unroll
        for (int j = 0; j < 8; j++) {
            mx0 = fmaxf(mx0, fmaxf(sv[j][0], sv[j][1]));
            mx1 = fmaxf(mx1, fmaxf(sv[j][2], sv[j][3]));
        }
        mx0 = fmaxf(mx0, __shfl_xor_sync(0xffffffffu, mx0, 1));
        mx0 = fmaxf(mx0, __shfl_xor_sync(0xffffffffu, mx0, 2));
        mx1 = fmaxf(mx1, __shfl_xor_sync(0xffffffffu, mx1, 1));
        mx1 = fmaxf(mx1, __shfl_xor_sync(0xffffffffu, mx1, 2));

        const float mn0 = fmaxf(m0, mx0), mn1 = fmaxf(m1, mx1);
        const float cr0 = __expf(m0 - mn0), cr1 = __expf(m1 - mn1);
        float s0 = 0.0f, s1 = 0.0f;
#pragma unroll
        for (int j = 0; j < 8; j++) {
            sv[j][0] = __expf(sv[j][0] - mn0);
            sv[j][1] = __expf(sv[j][1] - mn0);
            sv[j][2] = __expf(sv[j][2] - mn1);
            sv[j][3] = __expf(sv[j][3] - mn1);
            s0 += sv[j][0] + sv[j][1];
            s1 += sv[j][2] + sv[j][3];
        }
        s0 += __shfl_xor_sync(0xffffffffu, s0, 1);
        s0 += __shfl_xor_sync(0xffffffffu, s0, 2);
        s1 += __shfl_xor_sync(0xffffffffu, s1, 1);
        s1 += __shfl_xor_sync(0xffffffffu, s1, 2);
        l0 = l0 * cr0 + s0;  m0 = mn0;
        l1 = l1 * cr1 + s1;  m1 = mn1;
#pragma unroll
        for (int n = 0; n < 16; n++) {
            ov[n][0] *= cr0; ov[n][1] *= cr0;
            ov[n][2] *= cr1; ov[n][3] *= cr1;
        }

        // ---- P fragments (hi/lo) directly from S registers ----
        uint32_t phi[4][4], plo[4][4];
#pragma unroll
        for (int t2 = 0; t2 < 4; t2++) {
            phi[t2][0] = pack_hi(sv[2 * t2][0],     sv[2 * t2][1]);
            plo[t2][0] = pack_lo(sv[2 * t2][0],     sv[2 * t2][1]);
            phi[t2][1] = pack_hi(sv[2 * t2][2],     sv[2 * t2][3]);
            plo[t2][1] = pack_lo(sv[2 * t2][2],     sv[2 * t2][3]);
            phi[t2][2] = pack_hi(sv[2 * t2 + 1][0], sv[2 * t2 + 1][1]);
            plo[t2][2] = pack_lo(sv[2 * t2 + 1][0], sv[2 * t2 + 1][1]);
            phi[t2][3] = pack_hi(sv[2 * t2 + 1][2], sv[2 * t2 + 1][3]);
            plo[t2][3] = pack_lo(sv[2 * t2 + 1][2], sv[2 * t2 + 1][3]);
        }

        // ---- O += P V (3-term) ----
#pragma unroll
        for (int t2 = 0; t2 < 4; t2++) {
#pragma unroll
            for (int jj = 0; jj < 8; jj++) {
                uint32_t vh[4], vl[4];
                int r = 16 * t2 + lr, d = 16 * jj + lc;
                uint32_t a = kvb + 32768 + r * 256 + (((d >> 3) ^ (r & 7)) << 4);
                LDSM_X4_T(vh[0], vh[1], vh[2], vh[3], a);
                LDSM_X4_T(vl[0], vl[1], vl[2], vl[3], a + 16384);
                uint32_t b0[2] = {vh[0], vh[1]}, b1[2] = {vh[2], vh[3]};
                uint32_t c0[2] = {vl[0], vl[1]}, c1[2] = {vl[2], vl[3]};
                MMA_BF16(ov[2 * jj],     phi[t2], b0);
                MMA_BF16(ov[2 * jj],     plo[t2], b0);
                MMA_BF16(ov[2 * jj],     phi[t2], c0);
                MMA_BF16(ov[2 * jj + 1], phi[t2], b1);
                MMA_BF16(ov[2 * jj + 1], plo[t2], b1);
                MMA_BF16(ov[2 * jj + 1], phi[t2], c1);
            }
        }
    }

    // ---- epilogue: normalize and write hi/lo bf16 ----
    const float inv0 = 1.0f / l0, inv1 = 1.0f / l1;
    const size_t base0 = (size_t)r0g * HID + h * HD + (lane & 3) * 2;
    const size_t base1 = base0 + (size_t)8 * HID;
#pragma unroll
    for (int n = 0; n < 16; n++) {
        float x0 = ov[n][0] * inv0, x1 = ov[n][1] * inv0;
        float y0 = ov[n][2] * inv1, y1 = ov[n][3] * inv1;
        *(uint32_t*)&Ohi[base0 + 8 * n] = pack_hi(x0, x1);
        *(uint32_t*)&Olo[base0 + 8 * n] = pack_lo(x0, x1);
        *(uint32_t*)&Ohi[base1 + 8 * n] = pack_hi(y0, y1);
        *(uint32_t*)&Olo[base1 + 8 * n] = pack_lo(y0, y1);
    }
}

// ---------------------------------------------------------------------------

extern "C" void kernel_launch(void* const* d_in, const int* in_sizes, int n_in,
                              void* d_out, int out_size)
{
    const float* X  = (const float*)d_in[0];
    const float* Wq = (const float*)d_in[1];
    const float* Wk = (const float*)d_in[2];
    const float* Wv = (const float*)d_in[3];
    const float* Wo = (const float*)d_in[4];
    float* out = (float*)d_out;

    __nv_bfloat16 *xhi, *xlo, *qhi, *qlo, *khi, *klo, *vhi, *vlo, *aohi, *aolo;
    __nv_bfloat16 *wqh, *wql, *wkh, *wkl, *wvh, *wvl, *woh, *wol;
    cudaGetSymbolAddress((void**)&xhi,  g_Xhi);
    cudaGetSymbolAddress((void**)&xlo,  g_Xlo);
    cudaGetSymbolAddress((void**)&qhi,  g_Qhi);
    cudaGetSymbolAddress((void**)&qlo,  g_Qlo);
    cudaGetSymbolAddress((void**)&khi,  g_Khi);
    cudaGetSymbolAddress((void**)&klo,  g_Klo);
    cudaGetSymbolAddress((void**)&vhi,  g_Vhi);
    cudaGetSymbolAddress((void**)&vlo,  g_Vlo);
    cudaGetSymbolAddress((void**)&aohi, g_AOhi);
    cudaGetSymbolAddress((void**)&aolo, g_AOlo);
    cudaGetSymbolAddress((void**)&wqh,  g_Wqhi);
    cudaGetSymbolAddress((void**)&wql,  g_Wqlo);
    cudaGetSymbolAddress((void**)&wkh,  g_Wkhi);
    cudaGetSymbolAddress((void**)&wkl,  g_Wklo);
    cudaGetSymbolAddress((void**)&wvh,  g_Wvhi);
    cudaGetSymbolAddress((void**)&wvl,  g_Wvlo);
    cudaGetSymbolAddress((void**)&woh,  g_Wohi);
    cudaGetSymbolAddress((void**)&wol,  g_Wolo);

    cudaFuncSetAttribute(gemm_mma_kernel<true>,
                         cudaFuncAttributeMaxDynamicSharedMemorySize, GEMM_SMEM);
    cudaFuncSetAttribute(gemm_mma_kernel<false>,
                         cudaFuncAttributeMaxDynamicSharedMemorySize, GEMM_SMEM);
    cudaFuncSetAttribute(attn_mma_kernel,
                         cudaFuncAttributeMaxDynamicSharedMemorySize, ATTN_SMEM);

    const int xblocks = SEQ * HID / 4 / 256;   // 8192
    const int wblocks = HID * HID / 4 / 256;   // 4096
    dim3 gg(HID / 128, SEQ / 128);             // (16, 32)

    split_kernel<<<xblocks, 256>>>(X, xhi, xlo);
    split_kernel<<<wblocks, 256>>>(Wq, wqh, wql);
    split_kernel<<<wblocks, 256>>>(Wk, wkh, wkl);
    split_kernel<<<wblocks, 256>>>(Wv, wvh, wvl);
    split_kernel<<<wblocks, 256>>>(Wo, woh, wol);

    gemm_mma_kernel<true><<<gg, 256, GEMM_SMEM>>>(xhi, xlo, wqh, wql, nullptr, qhi, qlo);
    gemm_mma_kernel<true><<<gg, 256, GEMM_SMEM>>>(xhi, xlo, wkh, wkl, nullptr, khi, klo);
    gemm_mma_kernel<true><<<gg, 256, GEMM_SMEM>>>(xhi, xlo, wvh, wvl, nullptr, vhi, vlo);

    attn_mma_kernel<<<dim3(SEQ / 128, NH), 256, ATTN_SMEM>>>(
        qhi, qlo, khi, klo, vhi, vlo, aohi, aolo);

    gemm_mma_kernel<false><<<gg, 256, GEMM_SMEM>>>(aohi, aolo, woh, wol, out, nullptr, nullptr);
}

// round 12
// speedup vs baseline: 4.0729x; 1.1105x over previous
#include <cuda_runtime.h>
#include <cuda_bf16.h>
#include <math.h>
#include <stdint.h>

#define SEQ      4096
#define HID      2048
#define NH       16
#define HD       128
#define HALF_WIN 256
#define NGLOB    16
#define SCALE    0.08838834764831845f   // 128^-0.5

// GEMM tiling (mma.sync path)
#define KCH        32
#define NKCHUNK    (HID / KCH)       // 64
#define STAGE_B    32768             // Ah 8K | Al 8K | Bh 8K | Bl 8K
#define NSTAGES    3
#define GEMM_SMEM  (NSTAGES * STAGE_B)   // 98304

// Attention smem: Qhi 32K | Qlo 32K | 2 KV stages (Khi|Klo|Vhi|Vlo = 64K each)
#define ATTN_SMEM  (65536 + 2 * 65536)   // 196608

// Single dynamic-smem declaration shared by all kernels in this TU.
extern __shared__ __align__(1024) char dyn_smem[];

// ---------------------------------------------------------------------------
// Scratch (device globals: allocation-free rule)
// ---------------------------------------------------------------------------
__device__ __nv_bfloat16 g_Xhi[SEQ * HID], g_Xlo[SEQ * HID];
__device__ __nv_bfloat16 g_Qhi[SEQ * HID], g_Qlo[SEQ * HID];
__device__ __nv_bfloat16 g_Khi[SEQ * HID], g_Klo[SEQ * HID];
__device__ __nv_bfloat16 g_Vhi[SEQ * HID], g_Vlo[SEQ * HID];
__device__ __nv_bfloat16 g_AOhi[SEQ * HID], g_AOlo[SEQ * HID];
__device__ __nv_bfloat16 g_Wqhi[HID * HID], g_Wqlo[HID * HID];
__device__ __nv_bfloat16 g_Wkhi[HID * HID], g_Wklo[HID * HID];
__device__ __nv_bfloat16 g_Wvhi[HID * HID], g_Wvlo[HID * HID];
__device__ __nv_bfloat16 g_Wohi[HID * HID], g_Wolo[HID * HID];

// ---------------------------------------------------------------------------
// Helpers (sm_80-compatible PTX only: cp.async, ldmatrix, mma.sync)
// ---------------------------------------------------------------------------
__device__ __forceinline__ uint32_t smem_u32(const void* p) {
    uint32_t a;
    asm("{ .reg .u64 t; cvta.to.shared.u64 t, %1; cvt.u32.u64 %0, t; }" : "=r"(a) : "l"(p));
    return a;
}

__device__ __forceinline__ void cp16(uint32_t dst, const void* src) {
    asm volatile("cp.async.cg.shared.global [%0], [%1], 16;" :: "r"(dst), "l"(src));
}
#define CP_COMMIT() asm volatile("cp.async.commit_group;" ::: "memory")
#define CP_WAIT2()  asm volatile("cp.async.wait_group 2;" ::: "memory")
#define CP_WAIT1()  asm volatile("cp.async.wait_group 1;" ::: "memory")

#define LDSM_X4(r0, r1, r2, r3, addr) \
    asm volatile("ldmatrix.sync.aligned.m8n8.x4.shared.b16 {%0,%1,%2,%3}, [%4];" \
                 : "=r"(r0), "=r"(r1), "=r"(r2), "=r"(r3) : "r"(addr))

#define LDSM_X4_T(r0, r1, r2, r3, addr) \
    asm volatile("ldmatrix.sync.aligned.m8n8.x4.trans.shared.b16 {%0,%1,%2,%3}, [%4];" \
                 : "=r"(r0), "=r"(r1), "=r"(r2), "=r"(r3) : "r"(addr))

#define MMA_BF16(d, a, b) \
    asm volatile("mma.sync.aligned.m16n8k16.row.col.f32.bf16.bf16.f32 " \
                 "{%0,%1,%2,%3}, {%4,%5,%6,%7}, {%8,%9}, {%0,%1,%2,%3};" \
                 : "+f"((d)[0]), "+f"((d)[1]), "+f"((d)[2]), "+f"((d)[3]) \
                 : "r"((a)[0]), "r"((a)[1]), "r"((a)[2]), "r"((a)[3]), \
                   "r"((b)[0]), "r"((b)[1]))

__device__ __forceinline__ uint32_t pack_bf2(__nv_bfloat16 a, __nv_bfloat16 b) {
    return (uint32_t)__bfloat16_as_ushort(a) | ((uint32_t)__bfloat16_as_ushort(b) << 16);
}
__device__ __forceinline__ uint32_t pack_hi(float x, float y) {
    return pack_bf2(__float2bfloat16_rn(x), __float2bfloat16_rn(y));
}
__device__ __forceinline__ uint32_t pack_lo(float x, float y) {
    __nv_bfloat16 hx = __float2bfloat16_rn(x), hy = __float2bfloat16_rn(y);
    return pack_bf2(__float2bfloat16_rn(x - __bfloat162float(hx)),
                    __float2bfloat16_rn(y - __bfloat162float(hy)));
}

// ---------------------------------------------------------------------------
// Merged hi/lo split: one launch covers X (2 y-slices) + 4 weight matrices.
// grid = (4096, 6), 1024 elements per block.
// ---------------------------------------------------------------------------
__global__ __launch_bounds__(256) void split_all_kernel(
    const float* __restrict__ X,  __nv_bfloat16* __restrict__ xh,  __nv_bfloat16* __restrict__ xl,
    const float* __restrict__ W0, __nv_bfloat16* __restrict__ w0h, __nv_bfloat16* __restrict__ w0l,
    const float* __restrict__ W1, __nv_bfloat16* __restrict__ w1h, __nv_bfloat16* __restrict__ w1l,
    const float* __restrict__ W2, __nv_bfloat16* __restrict__ w2h, __nv_bfloat16* __restrict__ w2l,
    const float* __restrict__ W3, __nv_bfloat16* __restrict__ w3h, __nv_bfloat16* __restrict__ w3l)
{
    const int y = blockIdx.y;
    const float* src;
    __nv_bfloat16 *hi, *lo;
    size_t base = 0;
    switch (y) {
        case 0: src = X;  hi = xh;  lo = xl;  break;
        case 1: src = X;  hi = xh;  lo = xl;  base = (size_t)4096 * 1024; break;
        case 2: src = W0; hi = w0h; lo = w0l; break;
        case 3: src = W1; hi = w1h; lo = w1l; break;
        case 4: src = W2; hi = w2h; lo = w2l; break;
        default: src = W3; hi = w3h; lo = w3l; break;
    }
    size_t i = base + ((size_t)blockIdx.x * 256 + threadIdx.x) * 4;
    float4 x = *(const float4*)(src + i);
    float xs[4] = {x.x, x.y, x.z, x.w};
    __nv_bfloat16 h[4], l[4];
#pragma unroll
    for (int j = 0; j < 4; j++) {
        h[j] = __float2bfloat16_rn(xs[j]);
        l[j] = __float2bfloat16_rn(xs[j] - __bfloat162float(h[j]));
    }
    *(uint2*)(hi + i) = make_uint2(pack_bf2(h[0], h[1]), pack_bf2(h[2], h[3]));
    *(uint2*)(lo + i) = make_uint2(pack_bf2(l[0], l[1]), pack_bf2(l[2], l[3]));
}

// ---------------------------------------------------------------------------
// GEMM chunk loader
// ---------------------------------------------------------------------------
__device__ __forceinline__ void load_chunk(
    uint32_t sbase,
    const __nv_bfloat16* __restrict__ Ahi, const __nv_bfloat16* __restrict__ Alo,
    const __nv_bfloat16* __restrict__ Bhi, const __nv_bfloat16* __restrict__ Blo,
    int mtile, int ntile, int kc, int tid)
{
#pragma unroll
    for (int i = 0; i < 2; i++) {
        int unit = tid + i * 256;
        int r = unit >> 2, u = unit & 3;
        uint32_t dst = sbase + r * 64 + ((u ^ ((r >> 1) & 3)) << 4);
        size_t g = (size_t)(mtile * 128 + r) * HID + kc * KCH + u * 8;
        cp16(dst,        Ahi + g);
        cp16(dst + 8192, Alo + g);
    }
#pragma unroll
    for (int i = 0; i < 2; i++) {
        int unit = tid + i * 256;
        int r = unit >> 4, u = unit & 15;
        uint32_t dst = sbase + 16384 + r * 256 + ((u ^ (r & 7)) << 4);
        size_t g = (size_t)(kc * KCH + r) * HID + ntile * 128 + u * 8;
        cp16(dst,        Bhi + g);
        cp16(dst + 8192, Blo + g);
    }
}

// ---------------------------------------------------------------------------
// bf16 mma.sync GEMM body, 3-term hi/lo compensation.
// ---------------------------------------------------------------------------
template<bool SPLIT>
__device__ __forceinline__ void gemm_body(
    const __nv_bfloat16* __restrict__ Ahi, const __nv_bfloat16* __restrict__ Alo,
    const __nv_bfloat16* __restrict__ Bhi, const __nv_bfloat16* __restrict__ Blo,
    float* __restrict__ C,
    __nv_bfloat16* __restrict__ Ohi, __nv_bfloat16* __restrict__ Olo,
    int ntile, int mtile)
{
    const uint32_t sb = smem_u32(dyn_smem);
    const int tid  = threadIdx.x;
    const int lane = tid & 31;
    const int wid  = tid >> 5;
    const int wm = (wid & 1) * 64;
    const int wn = (wid >> 1) * 32;

    float acc[4][4][4];
#pragma unroll
    for (int a = 0; a < 4; a++)
#pragma unroll
        for (int b = 0; b < 4; b++)
#pragma unroll
            for (int c = 0; c < 4; c++) acc[a][b][c] = 0.0f;

#pragma unroll
    for (int s = 0; s < NSTAGES; s++) {
        load_chunk(sb + s * STAGE_B, Ahi, Alo, Bhi, Blo, mtile, ntile, s, tid);
        CP_COMMIT();
    }

    for (int c = 0; c < NKCHUNK; c++) {
        const int s = c % NSTAGES;
        const uint32_t sA  = sb + s * STAGE_B;
        const uint32_t sBh = sA + 16384;

        CP_WAIT2();
        __syncthreads();

#pragma unroll
        for (int ks = 0; ks < KCH; ks += 16) {
            uint32_t ah[4][4], bh[4][2], bl[4][2];

            const int brow = ks + (lane & 7) + ((lane >> 3) & 1) * 8;
            const int bnh  = (lane >> 4) * 8;
#pragma unroll
            for (int p = 0; p < 2; p++) {
                const int ncol = wn + p * 16 + bnh;
                uint32_t addr = sBh + brow * 256 + (((ncol >> 3) ^ (brow & 7)) << 4);
                uint32_t r0, r1, r2, r3;
                LDSM_X4_T(r0, r1, r2, r3, addr);
                bh[2 * p][0] = r0; bh[2 * p][1] = r1;
                bh[2 * p + 1][0] = r2; bh[2 * p + 1][1] = r3;
                LDSM_X4_T(r0, r1, r2, r3, addr + 8192);
                bl[2 * p][0] = r0; bl[2 * p][1] = r1;
                bl[2 * p + 1][0] = r2; bl[2 * p + 1][1] = r3;
            }

            const int au = (ks >> 3) + (lane >> 4);
#pragma unroll
            for (int mi = 0; mi < 4; mi++) {
                const int m = wm + mi * 16 + (lane & 15);
                uint32_t addr = sA + m * 64 + ((au ^ ((m >> 1) & 3)) << 4);
                LDSM_X4(ah[mi][0], ah[mi][1], ah[mi][2], ah[mi][3], addr);
            }
#pragma unroll
            for (int mi = 0; mi < 4; mi++)
#pragma unroll
                for (int ni = 0; ni < 4; ni++) {
                    MMA_BF16(acc[mi][ni], ah[mi], bh[ni]);
                    MMA_BF16(acc[mi][ni], ah[mi], bl[ni]);
                }
#pragma unroll
            for (int mi = 0; mi < 4; mi++) {
                const int m = wm + mi * 16 + (lane & 15);
                uint32_t addr = sA + 8192 + m * 64 + ((au ^ ((m >> 1) & 3)) << 4);
                LDSM_X4(ah[mi][0], ah[mi][1], ah[mi][2], ah[mi][3], addr);
            }
#pragma unroll
            for (int mi = 0; mi < 4; mi++)
#pragma unroll
                for (int ni = 0; ni < 4; ni++)
                    MMA_BF16(acc[mi][ni], ah[mi], bh[ni]);
        }

        __syncthreads();
        const int cn = c + NSTAGES;
        if (cn < NKCHUNK)
            load_chunk(sb + s * STAGE_B, Ahi, Alo, Bhi, Blo, mtile, ntile, cn, tid);
        CP_COMMIT();
    }

    const size_t cbase = (size_t)(mtile * 128) * HID + ntile * 128;
#pragma unroll
    for (int mi = 0; mi < 4; mi++) {
#pragma unroll
        for (int ni = 0; ni < 4; ni++) {
            const int r0  = wm + mi * 16 + (lane >> 2);
            const int col = wn + ni * 8 + (lane & 3) * 2;
            const size_t i0 = cbase + (size_t)r0 * HID + col;
            const size_t i1 = i0 + 8 * HID;
            if (SPLIT) {
                *(uint32_t*)&Ohi[i0] = pack_hi(acc[mi][ni][0], acc[mi][ni][1]);
                *(uint32_t*)&Olo[i0] = pack_lo(acc[mi][ni][0], acc[mi][ni][1]);
                *(uint32_t*)&Ohi[i1] = pack_hi(acc[mi][ni][2], acc[mi][ni][3]);
                *(uint32_t*)&Olo[i1] = pack_lo(acc[mi][ni][2], acc[mi][ni][3]);
            } else {
                *(float2*)&C[i0] = make_float2(acc[mi][ni][0], acc[mi][ni][1]);
                *(float2*)&C[i1] = make_float2(acc[mi][ni][2], acc[mi][ni][3]);
            }
        }
    }
}

// QKV: one launch, grid (16, 32, 3); z selects weight + destination.
__global__ __launch_bounds__(256, 2) void qkv_gemm_kernel(
    const __nv_bfloat16* __restrict__ Ahi, const __nv_bfloat16* __restrict__ Alo,
    const __nv_bfloat16* __restrict__ W0h, const __nv_bfloat16* __restrict__ W0l,
    __nv_bfloat16* __restrict__ O0h, __nv_bfloat16* __restrict__ O0l,
    const __nv_bfloat16* __restrict__ W1h, const __nv_bfloat16* __restrict__ W1l,
    __nv_bfloat16* __restrict__ O1h, __nv_bfloat16* __restrict__ O1l,
    const __nv_bfloat16* __restrict__ W2h, const __nv_bfloat16* __restrict__ W2l,
    __nv_bfloat16* __restrict__ O2h, __nv_bfloat16* __restrict__ O2l)
{
    const __nv_bfloat16 *bh, *bl;
    __nv_bfloat16 *oh, *ol;
    if (blockIdx.z == 0)      { bh = W0h; bl = W0l; oh = O0h; ol = O0l; }
    else if (blockIdx.z == 1) { bh = W1h; bl = W1l; oh = O1h; ol = O1l; }
    else                      { bh = W2h; bl = W2l; oh = O2h; ol = O2l; }
    gemm_body<true>(Ahi, Alo, bh, bl, nullptr, oh, ol, blockIdx.x, blockIdx.y);
}

__global__ __launch_bounds__(256, 2) void out_gemm_kernel(
    const __nv_bfloat16* __restrict__ Ahi, const __nv_bfloat16* __restrict__ Alo,
    const __nv_bfloat16* __restrict__ Bhi, const __nv_bfloat16* __restrict__ Blo,
    float* __restrict__ C)
{
    gemm_body<false>(Ahi, Alo, Bhi, Blo, C, nullptr, nullptr, blockIdx.x, blockIdx.y);
}

// ---------------------------------------------------------------------------
// Flash attention, mma.sync bf16 with hi/lo compensation.
// Block: 128 queries x 1 head, 256 threads (8 warps, 16 q rows each).
// Global rows (0..15) live in warp 0 of block x==0: that block runs far KV
// tiles with warp-0-only compute (other warps skip; their masked state is
// unchanged either way).
// ---------------------------------------------------------------------------
__device__ __forceinline__ void attn_load_kv(
    uint32_t kvb, int t, int tid, int h,
    const __nv_bfloat16* __restrict__ Khi, const __nv_bfloat16* __restrict__ Klo,
    const __nv_bfloat16* __restrict__ Vhi, const __nv_bfloat16* __restrict__ Vlo)
{
#pragma unroll
    for (int i = 0; i < 4; i++) {
        int u = tid + 256 * i;
        int r = u >> 4, c = u & 15;
        size_t g = (size_t)(t * 64 + r) * HID + h * HD + c * 8;
        uint32_t dst = kvb + r * 256 + ((c ^ (r & 7)) << 4);
        cp16(dst,         Khi + g);
        cp16(dst + 16384, Klo + g);
        cp16(dst + 32768, Vhi + g);
        cp16(dst + 49152, Vlo + g);
    }
}

__global__ __launch_bounds__(256, 1) void attn_mma_kernel(
    const __nv_bfloat16* __restrict__ Qhi, const __nv_bfloat16* __restrict__ Qlo,
    const __nv_bfloat16* __restrict__ Khi, const __nv_bfloat16* __restrict__ Klo,
    const __nv_bfloat16* __restrict__ Vhi, const __nv_bfloat16* __restrict__ Vlo,
    __nv_bfloat16* __restrict__ Ohi, __nv_bfloat16* __restrict__ Olo)
{
    const uint32_t sb = smem_u32(dyn_smem);
    const uint32_t SQ = sb;                     // Qhi 32K, Qlo at +32768
    const int tid = threadIdx.x, lane = tid & 31, wid = tid >> 5;
    const int wm = wid * 16;
    const int q0 = blockIdx.x * 128;
    const int h  = blockIdx.y;
    const int lr = lane & 15, lc = (lane >> 4) * 8;

    // Q tile load (hi+lo)
#pragma unroll
    for (int i = 0; i < 8; i++) {
        int u = tid + 256 * i;
        int r = u >> 4, c = u & 15;
        size_t g = (size_t)(q0 + r) * HID + h * HD + c * 8;
        uint32_t dst = SQ + r * 256 + ((c ^ (r & 7)) << 4);
        cp16(dst,         Qhi + g);
        cp16(dst + 32768, Qlo + g);
    }
    CP_COMMIT();

    int t_lo, t_hi;
    {
        int lo = q0 - (HALF_WIN - 1);
        t_lo = (lo < 64) ? 1 : (lo >> 6);
        t_hi = (q0 + 127 + HALF_WIN - 1) >> 6;
        if (t_hi > 63) t_hi = 63;
    }
    // block x==0: continue past band so warp 0 (global rows 0..15) sees all keys
    const int n_tiles = (q0 == 0) ? 64 : (t_hi - t_lo + 2);

    attn_load_kv(sb + 65536, 0, tid, h, Khi, Klo, Vhi, Vlo);
    CP_COMMIT();

    float m0 = -INFINITY, m1 = -INFINITY, l0 = 0.0f, l1 = 0.0f;
    float ov[16][4];
#pragma unroll
    for (int n = 0; n < 16; n++)
#pragma unroll
        for (int c = 0; c < 4; c++) ov[n][c] = 0.0f;

    const int r0g = q0 + wm + (lane >> 2);
    const int r1g = r0g + 8;

    for (int it = 0; it < n_tiles; it++) {
        const int s = it & 1;
        const uint32_t kvb = sb + 65536 + s * 65536;

        __syncthreads();               // prev compute done before stage reuse
        if (it + 1 < n_tiles)
            attn_load_kv(sb + 65536 + (s ^ 1) * 65536, t_lo + it, tid, h,
                         Khi, Klo, Vhi, Vlo);
        CP_COMMIT();
        CP_WAIT1();
        __syncthreads();               // current tile visible to all threads

        const int t   = (it == 0) ? 0 : (t_lo + it - 1);
        const int kv0 = t << 6;
        const bool far = (q0 == 0) && (t > t_hi);

        if (!far || wid == 0) {
            // ---- S = Q K^T (3-term) ----
            float sv[8][4];
#pragma unroll
            for (int j = 0; j < 8; j++)
#pragma unroll
                for (int c = 0; c < 4; c++) sv[j][c] = 0.0f;

#pragma unroll
            for (int ks = 0; ks < 8; ks++) {
                uint32_t qh[4], ql[4];
                {
                    int r = wm + lr, d = 16 * ks + lc;
                    uint32_t a = SQ + r * 256 + (((d >> 3) ^ (r & 7)) << 4);
                    LDSM_X4(qh[0], qh[1], qh[2], qh[3], a);
                    LDSM_X4(ql[0], ql[1], ql[2], ql[3], a + 32768);
                }
#pragma unroll
                for (int j4 = 0; j4 < 4; j4++) {
                    uint32_t kh[4], kl[4];
                    int r = 16 * j4 + lr, d = 16 * ks + lc;
                    uint32_t a = kvb + r * 256 + (((d >> 3) ^ (r & 7)) << 4);
                    LDSM_X4(kh[0], kh[1], kh[2], kh[3], a);
                    LDSM_X4(kl[0], kl[1], kl[2], kl[3], a + 16384);
                    uint32_t b0[2] = {kh[0], kh[2]}, b1[2] = {kh[1], kh[3]};
                    uint32_t c0[2] = {kl[0], kl[2]}, c1[2] = {kl[1], kl[3]};
                    MMA_BF16(sv[2 * j4],     qh, b0);
                    MMA_BF16(sv[2 * j4],     qh, c0);
                    MMA_BF16(sv[2 * j4],     ql, b0);
                    MMA_BF16(sv[2 * j4 + 1], qh, b1);
                    MMA_BF16(sv[2 * j4 + 1], qh, c1);
                    MMA_BF16(sv[2 * j4 + 1], ql, b1);
                }
            }

            // ---- scale + mask ----
#pragma unroll
            for (int j = 0; j < 8; j++) {
                const int kc = kv0 + 8 * j + (lane & 3) * 2;
#pragma unroll
                for (int c = 0; c < 4; c++) {
                    const int qi = (c < 2) ? r0g : r1g;
                    const int kj = kc + (c & 1);
                    const int d  = qi - kj;
                    const bool ok = (d < HALF_WIN && d > -HALF_WIN) ||
                                    (qi < NGLOB) || (kj < NGLOB);
                    sv[j][c] = ok ? sv[j][c] * SCALE : -INFINITY;
                }
            }

            // ---- online softmax (2 rows per thread) ----
            float mx0 = -INFINITY, mx1 = -INFINITY;
#pragma unroll
            for (int j = 0; j < 8; j++) {
                mx0 = fmaxf(mx0, fmaxf(sv[j][0], sv[j][1]));
                mx1 = fmaxf(mx1, fmaxf(sv[j][2], sv[j][3]));
            }
            mx0 = fmaxf(mx0, __shfl_xor_sync(0xffffffffu, mx0, 1));
            mx0 = fmaxf(mx0, __shfl_xor_sync(0xffffffffu, mx0, 2));
            mx1 = fmaxf(mx1, __shfl_xor_sync(0xffffffffu, mx1, 1));
            mx1 = fmaxf(mx1, __shfl_xor_sync(0xffffffffu, mx1, 2));

            const float mn0 = fmaxf(m0, mx0), mn1 = fmaxf(m1, mx1);
            const float cr0 = __expf(m0 - mn0), cr1 = __expf(m1 - mn1);
            float s0 = 0.0f, s1 = 0.0f;
#pragma unroll
            for (int j = 0; j < 8; j++) {
                sv[j][0] = __expf(sv[j][0] - mn0);
                sv[j][1] = __expf(sv[j][1] - mn0);
                sv[j][2] = __expf(sv[j][2] - mn1);
                sv[j][3] = __expf(sv[j][3] - mn1);
                s0 += sv[j][0] + sv[j][1];
                s1 += sv[j][2] + sv[j][3];
            }
            s0 += __shfl_xor_sync(0xffffffffu, s0, 1);
            s0 += __shfl_xor_sync(0xffffffffu, s0, 2);
            s1 += __shfl_xor_sync(0xffffffffu, s1, 1);
            s1 += __shfl_xor_sync(0xffffffffu, s1, 2);
            l0 = l0 * cr0 + s0;  m0 = mn0;
            l1 = l1 * cr1 + s1;  m1 = mn1;
#pragma unroll
            for (int n = 0; n < 16; n++) {
                ov[n][0] *= cr0; ov[n][1] *= cr0;
                ov[n][2] *= cr1; ov[n][3] *= cr1;
            }

            // ---- P fragments (hi/lo) directly from S registers ----
            uint32_t phi[4][4], plo[4][4];
#pragma unroll
            for (int t2 = 0; t2 < 4; t2++) {
                phi[t2][0] = pack_hi(sv[2 * t2][0],     sv[2 * t2][1]);
                plo[t2][0] = pack_lo(sv[2 * t2][0],     sv[2 * t2][1]);
                phi[t2][1] = pack_hi(sv[2 * t2][2],     sv[2 * t2][3]);
                plo[t2][1] = pack_lo(sv[2 * t2][2],     sv[2 * t2][3]);
                phi[t2][2] = pack_hi(sv[2 * t2 + 1][0], sv[2 * t2 + 1][1]);
                plo[t2][2] = pack_lo(sv[2 * t2 + 1][0], sv[2 * t2 + 1][1]);
                phi[t2][3] = pack_hi(sv[2 * t2 + 1][2], sv[2 * t2 + 1][3]);
                plo[t2][3] = pack_lo(sv[2 * t2 + 1][2], sv[2 * t2 + 1][3]);
            }

            // ---- O += P V (3-term) ----
#pragma unroll
            for (int t2 = 0; t2 < 4; t2++) {
#pragma unroll
                for (int jj = 0; jj < 8; jj++) {
                    uint32_t vh[4], vl[4];
                    int r = 16 * t2 + lr, d = 16 * jj + lc;
                    uint32_t a = kvb + 32768 + r * 256 + (((d >> 3) ^ (r & 7)) << 4);
                    LDSM_X4_T(vh[0], vh[1], vh[2], vh[3], a);
                    LDSM_X4_T(vl[0], vl[1], vl[2], vl[3], a + 16384);
                    uint32_t b0[2] = {vh[0], vh[1]}, b1[2] = {vh[2], vh[3]};
                    uint32_t c0[2] = {vl[0], vl[1]}, c1[2] = {vl[2], vl[3]};
                    MMA_BF16(ov[2 * jj],     phi[t2], b0);
                    MMA_BF16(ov[2 * jj],     plo[t2], b0);
                    MMA_BF16(ov[2 * jj],     phi[t2], c0);
                    MMA_BF16(ov[2 * jj + 1], phi[t2], b1);
                    MMA_BF16(ov[2 * jj + 1], plo[t2], b1);
                    MMA_BF16(ov[2 * jj + 1], phi[t2], c1);
                }
            }
        }
    }

    // ---- epilogue: normalize and write hi/lo bf16 ----
    const float inv0 = 1.0f / l0, inv1 = 1.0f / l1;
    const size_t base0 = (size_t)r0g * HID + h * HD + (lane & 3) * 2;
    const size_t base1 = base0 + (size_t)8 * HID;
#pragma unroll
    for (int n = 0; n < 16; n++) {
        float x0 = ov[n][0] * inv0, x1 = ov[n][1] * inv0;
        float y0 = ov[n][2] * inv1, y1 = ov[n][3] * inv1;
        *(uint32_t*)&Ohi[base0 + 8 * n] = pack_hi(x0, x1);
        *(uint32_t*)&Olo[base0 + 8 * n] = pack_lo(x0, x1);
        *(uint32_t*)&Ohi[base1 + 8 * n] = pack_hi(y0, y1);
        *(uint32_t*)&Olo[base1 + 8 * n] = pack_lo(y0, y1);
    }
}

// ---------------------------------------------------------------------------

extern "C" void kernel_launch(void* const* d_in, const int* in_sizes, int n_in,
                              void* d_out, int out_size)
{
    const float* X  = (const float*)d_in[0];
    const float* Wq = (const float*)d_in[1];
    const float* Wk = (const float*)d_in[2];
    const float* Wv = (const float*)d_in[3];
    const float* Wo = (const float*)d_in[4];
    float* out = (float*)d_out;

    __nv_bfloat16 *xhi, *xlo, *qhi, *qlo, *khi, *klo, *vhi, *vlo, *aohi, *aolo;
    __nv_bfloat16 *wqh, *wql, *wkh, *wkl, *wvh, *wvl, *woh, *wol;
    cudaGetSymbolAddress((void**)&xhi,  g_Xhi);
    cudaGetSymbolAddress((void**)&xlo,  g_Xlo);
    cudaGetSymbolAddress((void**)&qhi,  g_Qhi);
    cudaGetSymbolAddress((void**)&qlo,  g_Qlo);
    cudaGetSymbolAddress((void**)&khi,  g_Khi);
    cudaGetSymbolAddress((void**)&klo,  g_Klo);
    cudaGetSymbolAddress((void**)&vhi,  g_Vhi);
    cudaGetSymbolAddress((void**)&vlo,  g_Vlo);
    cudaGetSymbolAddress((void**)&aohi, g_AOhi);
    cudaGetSymbolAddress((void**)&aolo, g_AOlo);
    cudaGetSymbolAddress((void**)&wqh,  g_Wqhi);
    cudaGetSymbolAddress((void**)&wql,  g_Wqlo);
    cudaGetSymbolAddress((void**)&wkh,  g_Wkhi);
    cudaGetSymbolAddress((void**)&wkl,  g_Wklo);
    cudaGetSymbolAddress((void**)&wvh,  g_Wvhi);
    cudaGetSymbolAddress((void**)&wvl,  g_Wvlo);
    cudaGetSymbolAddress((void**)&woh,  g_Wohi);
    cudaGetSymbolAddress((void**)&wol,  g_Wolo);

    cudaFuncSetAttribute(qkv_gemm_kernel,
                         cudaFuncAttributeMaxDynamicSharedMemorySize, GEMM_SMEM);
    cudaFuncSetAttribute(out_gemm_kernel,
                         cudaFuncAttributeMaxDynamicSharedMemorySize, GEMM_SMEM);
    cudaFuncSetAttribute(attn_mma_kernel,
                         cudaFuncAttributeMaxDynamicSharedMemorySize, ATTN_SMEM);

    split_all_kernel<<<dim3(4096, 6), 256>>>(
        X, xhi, xlo, Wq, wqh, wql, Wk, wkh, wkl, Wv, wvh, wvl, Wo, woh, wol);

    qkv_gemm_kernel<<<dim3(HID / 128, SEQ / 128, 3), 256, GEMM_SMEM>>>(
        xhi, xlo,
        wqh, wql, qhi, qlo,
        wkh, wkl, khi, klo,
        wvh, wvl, vhi, vlo);

    attn_mma_kernel<<<dim3(SEQ / 128, NH), 256, ATTN_SMEM>>>(
        qhi, qlo, khi, klo, vhi, vlo, aohi, aolo);

    out_gemm_kernel<<<dim3(HID / 128, SEQ / 128), 256, GEMM_SMEM>>>(
        aohi, aolo, woh, wol, out);
}